// round 10
// baseline (speedup 1.0000x reference)
#include <cuda_runtime.h>
#include <cuda_bf16.h>
#include <cstdint>

#define B_   4
#define L_   2048
#define H_   8
#define HD_  64
#define SCALE 0.125f
#define INV_ML (1.0f/2048.0f)

// ---------- device scratch ----------
__device__ __nv_bfloat16 xh_g[8192*256];
__device__ __nv_bfloat16 xl_g[8192*256];
__device__ __nv_bfloat16 Wth_g[1024*256];   // [Wq^T ; Wk^T], rows=n, cols=k
__device__ __nv_bfloat16 Wtl_g[1024*256];
__device__ __nv_bfloat16 Qh_g[32*2048*64];  // [h*4+b][l][hd]
__device__ __nv_bfloat16 Ql_g[32*2048*64];
__device__ __nv_bfloat16 Kh_g[32*2048*64];
__device__ __nv_bfloat16 Kl_g[32*2048*64];
__device__ float ptab_g[H_*4095];           // per-head SCALE*prior LUT

// ---------- helpers ----------
__device__ __forceinline__ void split2(float a, float b, uint32_t& hi, uint32_t& lo) {
    __nv_bfloat16 ah = __float2bfloat16(a), bh = __float2bfloat16(b);
    float ar = a - __bfloat162float(ah), br = b - __bfloat162float(bh);
    __nv_bfloat162 h2; h2.x = ah; h2.y = bh;
    __nv_bfloat162 l2; l2.x = __float2bfloat16(ar); l2.y = __float2bfloat16(br);
    hi = *(uint32_t*)&h2; lo = *(uint32_t*)&l2;
}

// NOTE: not volatile — outputs carry all dependencies; lets ptxas hoist
// the next fragment loads above these MMAs and interleave chains.
__device__ __forceinline__ void mma_bf16(float c[4], const uint32_t a[4],
                                         const uint32_t b[2]) {
    asm("mma.sync.aligned.m16n8k16.row.col.f32.bf16.bf16.f32 "
        "{%0,%1,%2,%3}, {%4,%5,%6,%7}, {%8,%9}, {%0,%1,%2,%3};"
        : "+f"(c[0]), "+f"(c[1]), "+f"(c[2]), "+f"(c[3])
        : "r"(a[0]), "r"(a[1]), "r"(a[2]), "r"(a[3]), "r"(b[0]), "r"(b[1]));
}

__device__ __forceinline__ void cpa16(uint32_t d, const void* s) {
    asm volatile("cp.async.cg.shared.global [%0], [%1], 16;" :: "r"(d), "l"(s));
}
__device__ __forceinline__ void cpa_commit() {
    asm volatile("cp.async.commit_group;" ::: "memory");
}
__device__ __forceinline__ void cpa_wait0() {
    asm volatile("cp.async.wait_group 0;" ::: "memory");
}
__device__ __forceinline__ void cpa_wait1() {
    asm volatile("cp.async.wait_group 1;" ::: "memory");
}

// ============================================================
// prep kernels
// ============================================================
__global__ __launch_bounds__(512) void ptab_kernel(const float* __restrict__ pm,
                                                   const float* __restrict__ ls) {
    int h = blockIdx.x;
    float mean = pm[h];
    float inv_std = __expf(-ls[h]);
    float cnorm = SCALE * inv_std * 0.39894228f;
    for (int t = threadIdx.x; t < 4095; t += 512) {
        float dd = (float)(t - 2047) * INV_ML;
        float z = (dd - mean) * inv_std;
        ptab_g[h * 4095 + t] = cnorm * __expf(-0.5f * z * z);
    }
}

__global__ __launch_bounds__(256) void conv_x_kernel(const float* __restrict__ x) {
    int i = blockIdx.x * 256 + threadIdx.x;   // float4 index, 524288 total
    float4 v = ((const float4*)x)[i];
    uint32_t h0, l0, h1, l1;
    split2(v.x, v.y, h0, l0);
    split2(v.z, v.w, h1, l1);
    ((uint2*)xh_g)[i] = make_uint2(h0, h1);
    ((uint2*)xl_g)[i] = make_uint2(l0, l1);
}

__global__ void conv_w_kernel(const float* __restrict__ Wq,
                              const float* __restrict__ Wk) {
    __shared__ float t[32][33];
    const float* W = blockIdx.z ? Wk : Wq;
    int n0 = blockIdx.x * 32, k0 = blockIdx.y * 32;
    int tx = threadIdx.x, ty = threadIdx.y;
#pragma unroll
    for (int i = 0; i < 32; i += 8)
        t[ty + i][tx] = W[(size_t)(k0 + ty + i) * 512 + n0 + tx];
    __syncthreads();
#pragma unroll
    for (int i = 0; i < 32; i += 8) {
        int n = n0 + ty + i, k = k0 + tx;
        float v = t[tx][ty + i];
        __nv_bfloat16 h = __float2bfloat16(v);
        float r = v - __bfloat162float(h);
        size_t o = (size_t)(blockIdx.z * 512 + n) * 256 + k;
        Wth_g[o] = h;
        Wtl_g[o] = __float2bfloat16(r);
    }
}

// ============================================================
// proj: [xh|xl][8192,256] @ Wt^T -> Q/K hi/lo bf16 in [h][b][l][hd]
// CTA 128x128, k-chunk 32 double-buffered, 2 CTAs/SM.
// ============================================================
#define PJ_SMEM (10240*4*2)

__global__ __launch_bounds__(256, 2) void proj_kernel(const float* __restrict__ bq,
                                                      const float* __restrict__ bk) {
    extern __shared__ uint32_t sm[];
    const int tid = threadIdx.x;
    const int w = tid >> 5, lane = tid & 31, tg = lane >> 2, tm = lane & 3;
    const int mg = w & 3, ng = w >> 2;
    const int m0 = blockIdx.x * 128, n0 = blockIdx.y * 128;

    uint32_t smbase = (uint32_t)__cvta_generic_to_shared(sm);

    auto load_chunk = [&](int c, int buf) {
        uint32_t dst = smbase + (uint32_t)buf * 40960u;
#pragma unroll
        for (int i = 0; i < 2; i++) {
            int idx = i * 256 + tid;
            int row = idx >> 2, c4 = idx & 3;
            uint32_t so = (uint32_t)(row * 20 + c4 * 4) * 4;
            size_t goA = ((size_t)(m0 + row) * 256 + c * 32 + c4 * 8) * 2;  // bytes
            size_t goB = ((size_t)(n0 + row) * 256 + c * 32 + c4 * 8) * 2;
            cpa16(dst + so,          (const char*)xh_g  + goA);
            cpa16(dst + 10240 + so,  (const char*)xl_g  + goA);
            cpa16(dst + 20480 + so,  (const char*)Wth_g + goB);
            cpa16(dst + 30720 + so,  (const char*)Wtl_g + goB);
        }
        cpa_commit();
    };

    float acc[2][8][4];
#pragma unroll
    for (int mb = 0; mb < 2; mb++)
#pragma unroll
        for (int nb = 0; nb < 8; nb++)
#pragma unroll
            for (int j = 0; j < 4; j++) acc[mb][nb][j] = 0.f;

    load_chunk(0, 0);

#pragma unroll 1
    for (int c = 0; c < 8; c++) {
        const int buf = c & 1;
        if (c < 7) {
            load_chunk(c + 1, buf ^ 1);
            cpa_wait1();
        } else {
            cpa_wait0();
        }
        __syncthreads();

        const uint32_t* As_h = sm + buf * 10240;
        const uint32_t* As_l = As_h + 2560;
        const uint32_t* Bs_h = As_h + 5120;
        const uint32_t* Bs_l = As_h + 7680;

#pragma unroll
        for (int ks = 0; ks < 2; ks++) {
            const int ci = ks * 8 + tm;
            uint32_t ah[2][4], al[2][4];
#pragma unroll
            for (int mb = 0; mb < 2; mb++) {
                int rr = 32 * mg + 16 * mb + tg;
                ah[mb][0] = As_h[rr * 20 + ci];
                ah[mb][1] = As_h[(rr + 8) * 20 + ci];
                ah[mb][2] = As_h[rr * 20 + ci + 4];
                ah[mb][3] = As_h[(rr + 8) * 20 + ci + 4];
                al[mb][0] = As_l[rr * 20 + ci];
                al[mb][1] = As_l[(rr + 8) * 20 + ci];
                al[mb][2] = As_l[rr * 20 + ci + 4];
                al[mb][3] = As_l[(rr + 8) * 20 + ci + 4];
            }
#pragma unroll
            for (int nb = 0; nb < 8; nb++) {
                int rn = 64 * ng + 8 * nb + tg;
                uint32_t bh[2] = { Bs_h[rn * 20 + ci], Bs_h[rn * 20 + ci + 4] };
                uint32_t bl[2] = { Bs_l[rn * 20 + ci], Bs_l[rn * 20 + ci + 4] };
#pragma unroll
                for (int mb = 0; mb < 2; mb++) {
                    mma_bf16(acc[mb][nb], ah[mb], bh);
                    mma_bf16(acc[mb][nb], ah[mb], bl);
                    mma_bf16(acc[mb][nb], al[mb], bh);
                }
            }
        }
        __syncthreads();
    }

    // epilogue: bias, split, scatter to [h][b][l][hd]
#pragma unroll
    for (int mb = 0; mb < 2; mb++) {
        int r0 = m0 + 32 * mg + 16 * mb + tg;
#pragma unroll
        for (int nb = 0; nb < 8; nb++) {
            float* a = acc[mb][nb];
            int gcol = n0 + 64 * ng + 8 * nb + 2 * tm;
            int isK = gcol >> 9;
            const float* bias = isK ? bk : bq;
            int bi = gcol & 511;
            float b0 = bias[bi], b1 = bias[bi + 1];
            __nv_bfloat16* dh = isK ? Kh_g : Qh_g;
            __nv_bfloat16* dl = isK ? Kl_g : Ql_g;
            int hh = bi >> 6;
#pragma unroll
            for (int half = 0; half < 2; half++) {
                int r = r0 + 8 * half;
                int bb = r >> 11, l = r & 2047;
                float v0 = a[half * 2 + 0] + b0;
                float v1 = a[half * 2 + 1] + b1;
                uint32_t hi, lo;
                split2(v0, v1, hi, lo);
                size_t e = ((size_t)((hh * 4 + bb) * 2048 + l)) * 64 + (gcol & 63);
                *(uint32_t*)(dh + e) = hi;
                *(uint32_t*)(dl + e) = lo;
            }
        }
    }
}

// ============================================================
// flash: q-tile 128 x k-tile 64, 32 iters. Q hi/lo fragments in REGISTERS;
// K hi/lo in 3 rotating 18KB smem buffers via cp.async; 2 CTAs/SM.
// Odd linear CTAs spin ~1200 cyc before the mainloop to anti-phase the
// two co-resident CTAs (epilogue hides under partner's MMA).
// ============================================================
#define FL_SMEM ((13824 + 256) * 4)

__global__ __launch_bounds__(256, 2) void flash_kernel(float* __restrict__ out) {
    extern __shared__ uint32_t sm[];
    float* merge = (float*)(sm + 13824);   // 256 floats

    const int tid = threadIdx.x;
    const int w = tid >> 5, lane = tid & 31, tg = lane >> 2, tm = lane & 3;
    const int mg = w & 3, ng = w >> 2;
    const int q0 = blockIdx.x * 128;
    const int hb = blockIdx.y;
    const int h = hb >> 2;
    const size_t hb_off = (size_t)hb * 2048;

    uint32_t smbase = (uint32_t)__cvta_generic_to_shared(sm);

    // K tile kt (64 seq rows, hi+lo) -> buffer bi
    auto load_k = [&](int kt, int bi) {
        const char* gh = (const char*)(Kh_g + (hb_off + (size_t)kt * 64) * 64);
        const char* gl = (const char*)(Kl_g + (hb_off + (size_t)kt * 64) * 64);
        uint32_t dh = smbase + (uint32_t)bi * 18432u;
        uint32_t dl = dh + 9216u;
#pragma unroll
        for (int i = 0; i < 2; i++) {
            int idx = i * 256 + tid;
            int row = idx >> 3, c4 = idx & 7;
            uint32_t so = (uint32_t)(row * 36 + c4 * 4) * 4;
            size_t go = (size_t)row * 128 + c4 * 16;
            cpa16(dh + so, gh + go);
            cpa16(dl + so, gl + go);
        }
        cpa_commit();
    };

    // stage Q (hi->buf0 region, lo->buf1 region) as one group
    {
        const char* qh = (const char*)(Qh_g + (hb_off + q0) * 64);
        const char* ql = (const char*)(Ql_g + (hb_off + q0) * 64);
#pragma unroll
        for (int i = 0; i < 4; i++) {
            int idx = i * 256 + tid;
            int row = idx >> 3, c4 = idx & 7;
            uint32_t so = (uint32_t)(row * 36 + c4 * 4) * 4;
            size_t go = (size_t)row * 128 + c4 * 16;
            cpa16(smbase + so,           qh + go);
            cpa16(smbase + 18432u + so,  ql + go);
        }
        cpa_commit();
    }
    load_k(0, 2);          // K0 -> buf2 (K(j) -> buf (j+2)%3)

    cpa_wait1();           // Q group complete (K0 may still fly)
    __syncthreads();

    // Q fragments -> registers (once)
    uint32_t aqh[2][4][4], aql[2][4][4];
    {
        const uint32_t* Qs_h = sm;
        const uint32_t* Qs_l = sm + 4608;
#pragma unroll
        for (int mb = 0; mb < 2; mb++) {
            int rr = 32 * mg + 16 * mb + tg;
#pragma unroll
            for (int ks = 0; ks < 4; ks++) {
                int ci = ks * 8 + tm;
                aqh[mb][ks][0] = Qs_h[rr * 36 + ci];
                aqh[mb][ks][1] = Qs_h[(rr + 8) * 36 + ci];
                aqh[mb][ks][2] = Qs_h[rr * 36 + ci + 4];
                aqh[mb][ks][3] = Qs_h[(rr + 8) * 36 + ci + 4];
                aql[mb][ks][0] = Qs_l[rr * 36 + ci];
                aql[mb][ks][1] = Qs_l[(rr + 8) * 36 + ci];
                aql[mb][ks][2] = Qs_l[rr * 36 + ci + 4];
                aql[mb][ks][3] = Qs_l[(rr + 8) * 36 + ci + 4];
            }
        }
    }
    __syncthreads();       // all warps done reading staged Q
    load_k(1, 0);          // K1 -> buf0 (overwrites Q-hi region)

    // anti-phase stagger: odd linear CTAs delay ~1200 cycles so the two
    // co-resident CTAs interleave MMA and epilogue phases.
    if (((blockIdx.y * gridDim.x + blockIdx.x) & 1) != 0) {
        unsigned long long t0 = clock64();
        while (clock64() - t0 < 1200ull) { }
    }

    float suml[4] = {0.f, 0.f, 0.f, 0.f};
    float sumd[4] = {0.f, 0.f, 0.f, 0.f};
    const float* pt = ptab_g + h * 4095 + 2047;

#pragma unroll 1
    for (int kt = 0; kt < 32; kt++) {
        if (kt < 31) cpa_wait1();   // K(kt) done; K(kt+1) may fly
        else         cpa_wait0();
        __syncthreads();            // publish K(kt); K(kt-1) buffer free
        if (kt + 2 < 32) load_k(kt + 2, (kt + 1) % 3);

        const uint32_t* Kh = sm + ((kt + 2) % 3) * 4608;
        const uint32_t* Kl = Kh + 2304;

        float acc[2][4][4];
#pragma unroll
        for (int mb = 0; mb < 2; mb++)
#pragma unroll
            for (int nb = 0; nb < 4; nb++)
#pragma unroll
                for (int j = 0; j < 4; j++) acc[mb][nb][j] = 0.f;

#pragma unroll
        for (int ks = 0; ks < 4; ks++) {
            const int ci = ks * 8 + tm;
#pragma unroll
            for (int nb = 0; nb < 4; nb++) {
                int rn = 32 * ng + 8 * nb + tg;
                uint32_t bh[2] = { Kh[rn * 36 + ci], Kh[rn * 36 + ci + 4] };
                uint32_t bl[2] = { Kl[rn * 36 + ci], Kl[rn * 36 + ci + 4] };
#pragma unroll
                for (int mb = 0; mb < 2; mb++) {
                    mma_bf16(acc[mb][nb], aqh[mb][ks], bh);
                    mma_bf16(acc[mb][nb], aqh[mb][ks], bl);
                    mma_bf16(acc[mb][nb], aql[mb][ks], bh);
                }
            }
        }

        // epilogue: prior * score, exp, accumulate sum(p), sum(p*d)
        const int k0 = kt * 64;
#pragma unroll
        for (int mb = 0; mb < 2; mb++) {
            const int r0 = q0 + 32 * mg + 16 * mb + tg;
#pragma unroll
            for (int nb = 0; nb < 4; nb++) {
                const float* a = acc[mb][nb];
                int d0 = k0 + 32 * ng + 8 * nb + 2 * tm - r0;
                float fd = (float)d0;
                float p0 = __expf(a[0] * __ldg(pt + d0));
                float p1 = __expf(a[1] * __ldg(pt + d0 + 1));
                float p2 = __expf(a[2] * __ldg(pt + d0 - 8));
                float p3 = __expf(a[3] * __ldg(pt + d0 - 7));
                suml[2 * mb]     += p0 + p1;
                sumd[2 * mb]     += fmaf(p1, fd + 1.f, p0 * fd);
                suml[2 * mb + 1] += p2 + p3;
                sumd[2 * mb + 1] += fmaf(p3, fd - 7.f, p2 * (fd - 8.f));
            }
        }
    }

    // reduce across the 4 lanes of each group (width-4 shuffles)
#pragma unroll
    for (int s = 0; s < 4; s++) {
        suml[s] += __shfl_xor_sync(0xffffffffu, suml[s], 1, 4);
        suml[s] += __shfl_xor_sync(0xffffffffu, suml[s], 2, 4);
        sumd[s] += __shfl_xor_sync(0xffffffffu, sumd[s], 1, 4);
        sumd[s] += __shfl_xor_sync(0xffffffffu, sumd[s], 2, 4);
    }

    // merge the two n-groups via smem
    if (ng == 0 && tm == 0) {
#pragma unroll
        for (int s = 0; s < 4; s++) {
            int rl = 32 * mg + 16 * (s >> 1) + 8 * (s & 1) + tg;
            merge[rl] = suml[s];
            merge[128 + rl] = sumd[s];
        }
    }
    __syncthreads();
    if (ng == 1 && tm == 0) {
#pragma unroll
        for (int s = 0; s < 4; s++) {
            int rl = 32 * mg + 16 * (s >> 1) + 8 * (s & 1) + tg;
            float Lm = merge[rl] + suml[s];
            float Dm = merge[128 + rl] + sumd[s];
            out[((size_t)(hb & 3) * 2048 + q0 + rl) * 8 + h] = Dm * INV_ML / Lm;
        }
    }
}

// ============================================================
extern "C" void kernel_launch(void* const* d_in, const int* in_sizes, int n_in,
                              void* d_out, int out_size)
{
    const float* x  = (const float*)d_in[0];
    const float* Wq = (const float*)d_in[1];
    const float* bq = (const float*)d_in[2];
    const float* Wk = (const float*)d_in[3];
    const float* bk = (const float*)d_in[4];
    const float* pm = (const float*)d_in[5];
    const float* ls = (const float*)d_in[6];
    float* out = (float*)d_out;

    cudaFuncSetAttribute(proj_kernel,
                         cudaFuncAttributeMaxDynamicSharedMemorySize, PJ_SMEM);
    cudaFuncSetAttribute(flash_kernel,
                         cudaFuncAttributeMaxDynamicSharedMemorySize, FL_SMEM);

    ptab_kernel<<<8, 512>>>(pm, ls);
    conv_x_kernel<<<2048, 256>>>(x);
    conv_w_kernel<<<dim3(16, 8, 2), dim3(32, 8)>>>(Wq, Wk);
    proj_kernel<<<dim3(64, 8), 256, PJ_SMEM>>>(bq, bk);
    flash_kernel<<<dim3(16, 32), 256, FL_SMEM>>>(out);
}

// round 11
// speedup vs baseline: 1.5346x; 1.5346x over previous
#include <cuda_runtime.h>
#include <cuda_bf16.h>
#include <cstdint>

#define B_   4
#define L_   2048
#define H_   8
#define HD_  64
#define SCALE 0.125f
#define INV_ML (1.0f/2048.0f)

// ---------- device scratch ----------
__device__ __nv_bfloat16 xh_g[8192*256];
__device__ __nv_bfloat16 xl_g[8192*256];
__device__ __nv_bfloat16 Wth_g[1024*256];   // [Wq^T ; Wk^T], rows=n, cols=k
__device__ __nv_bfloat16 Wtl_g[1024*256];
__device__ __nv_bfloat16 Qh_g[32*2048*64];  // [h*4+b][l][hd]
__device__ __nv_bfloat16 Ql_g[32*2048*64];
__device__ __nv_bfloat16 Kh_g[32*2048*64];
__device__ __nv_bfloat16 Kl_g[32*2048*64];
__device__ float ptab_g[H_*4095];           // per-head SCALE*prior LUT

// ---------- helpers ----------
__device__ __forceinline__ void split2(float a, float b, uint32_t& hi, uint32_t& lo) {
    __nv_bfloat16 ah = __float2bfloat16(a), bh = __float2bfloat16(b);
    float ar = a - __bfloat162float(ah), br = b - __bfloat162float(bh);
    __nv_bfloat162 h2; h2.x = ah; h2.y = bh;
    __nv_bfloat162 l2; l2.x = __float2bfloat16(ar); l2.y = __float2bfloat16(br);
    hi = *(uint32_t*)&h2; lo = *(uint32_t*)&l2;
}

// volatile is load-bearing: R10 showed removing it regresses 1.5x
// (ptxas reschedules the chains pathologically).
__device__ __forceinline__ void mma_bf16(float c[4], const uint32_t a[4],
                                         const uint32_t b[2]) {
    asm volatile(
        "mma.sync.aligned.m16n8k16.row.col.f32.bf16.bf16.f32 "
        "{%0,%1,%2,%3}, {%4,%5,%6,%7}, {%8,%9}, {%0,%1,%2,%3};"
        : "+f"(c[0]), "+f"(c[1]), "+f"(c[2]), "+f"(c[3])
        : "r"(a[0]), "r"(a[1]), "r"(a[2]), "r"(a[3]), "r"(b[0]), "r"(b[1]));
}

__device__ __forceinline__ void cpa16(uint32_t d, const void* s) {
    asm volatile("cp.async.cg.shared.global [%0], [%1], 16;" :: "r"(d), "l"(s));
}
__device__ __forceinline__ void cpa_commit() {
    asm volatile("cp.async.commit_group;" ::: "memory");
}
__device__ __forceinline__ void cpa_wait0() {
    asm volatile("cp.async.wait_group 0;" ::: "memory");
}
__device__ __forceinline__ void cpa_wait1() {
    asm volatile("cp.async.wait_group 1;" ::: "memory");
}
__device__ __forceinline__ void cpa_wait2() {
    asm volatile("cp.async.wait_group 2;" ::: "memory");
}

// ============================================================
// prep kernels
// ============================================================
__global__ __launch_bounds__(512) void ptab_kernel(const float* __restrict__ pm,
                                                   const float* __restrict__ ls) {
    int h = blockIdx.x;
    float mean = pm[h];
    float inv_std = __expf(-ls[h]);
    float cnorm = SCALE * inv_std * 0.39894228f;
    for (int t = threadIdx.x; t < 4095; t += 512) {
        float dd = (float)(t - 2047) * INV_ML;
        float z = (dd - mean) * inv_std;
        ptab_g[h * 4095 + t] = cnorm * __expf(-0.5f * z * z);
    }
}

__global__ __launch_bounds__(256) void conv_x_kernel(const float* __restrict__ x) {
    int i = blockIdx.x * 256 + threadIdx.x;   // float4 index, 524288 total
    float4 v = ((const float4*)x)[i];
    uint32_t h0, l0, h1, l1;
    split2(v.x, v.y, h0, l0);
    split2(v.z, v.w, h1, l1);
    ((uint2*)xh_g)[i] = make_uint2(h0, h1);
    ((uint2*)xl_g)[i] = make_uint2(l0, l1);
}

__global__ void conv_w_kernel(const float* __restrict__ Wq,
                              const float* __restrict__ Wk) {
    __shared__ float t[32][33];
    const float* W = blockIdx.z ? Wk : Wq;
    int n0 = blockIdx.x * 32, k0 = blockIdx.y * 32;
    int tx = threadIdx.x, ty = threadIdx.y;
#pragma unroll
    for (int i = 0; i < 32; i += 8)
        t[ty + i][tx] = W[(size_t)(k0 + ty + i) * 512 + n0 + tx];
    __syncthreads();
#pragma unroll
    for (int i = 0; i < 32; i += 8) {
        int n = n0 + ty + i, k = k0 + tx;
        float v = t[tx][ty + i];
        __nv_bfloat16 h = __float2bfloat16(v);
        float r = v - __bfloat162float(h);
        size_t o = (size_t)(blockIdx.z * 512 + n) * 256 + k;
        Wth_g[o] = h;
        Wtl_g[o] = __float2bfloat16(r);
    }
}

// ============================================================
// proj: [xh|xl][8192,256] @ Wt^T -> Q/K hi/lo bf16 in [h][b][l][hd]
// CTA 128x128, k-chunk 32 double-buffered, 2 CTAs/SM.  (R9 config)
// ============================================================
#define PJ_SMEM (10240*4*2)

__global__ __launch_bounds__(256, 2) void proj_kernel(const float* __restrict__ bq,
                                                      const float* __restrict__ bk) {
    extern __shared__ uint32_t sm[];
    const int tid = threadIdx.x;
    const int w = tid >> 5, lane = tid & 31, tg = lane >> 2, tm = lane & 3;
    const int mg = w & 3, ng = w >> 2;
    const int m0 = blockIdx.x * 128, n0 = blockIdx.y * 128;

    uint32_t smbase = (uint32_t)__cvta_generic_to_shared(sm);

    auto load_chunk = [&](int c, int buf) {
        uint32_t dst = smbase + (uint32_t)buf * 40960u;
#pragma unroll
        for (int i = 0; i < 2; i++) {
            int idx = i * 256 + tid;
            int row = idx >> 2, c4 = idx & 3;
            uint32_t so = (uint32_t)(row * 20 + c4 * 4) * 4;
            size_t goA = ((size_t)(m0 + row) * 256 + c * 32 + c4 * 8) * 2;  // bytes
            size_t goB = ((size_t)(n0 + row) * 256 + c * 32 + c4 * 8) * 2;
            cpa16(dst + so,          (const char*)xh_g  + goA);
            cpa16(dst + 10240 + so,  (const char*)xl_g  + goA);
            cpa16(dst + 20480 + so,  (const char*)Wth_g + goB);
            cpa16(dst + 30720 + so,  (const char*)Wtl_g + goB);
        }
        cpa_commit();
    };

    float acc[2][8][4];
#pragma unroll
    for (int mb = 0; mb < 2; mb++)
#pragma unroll
        for (int nb = 0; nb < 8; nb++)
#pragma unroll
            for (int j = 0; j < 4; j++) acc[mb][nb][j] = 0.f;

    load_chunk(0, 0);

#pragma unroll 1
    for (int c = 0; c < 8; c++) {
        const int buf = c & 1;
        if (c < 7) {
            load_chunk(c + 1, buf ^ 1);
            cpa_wait1();
        } else {
            cpa_wait0();
        }
        __syncthreads();

        const uint32_t* As_h = sm + buf * 10240;
        const uint32_t* As_l = As_h + 2560;
        const uint32_t* Bs_h = As_h + 5120;
        const uint32_t* Bs_l = As_h + 7680;

#pragma unroll
        for (int ks = 0; ks < 2; ks++) {
            const int ci = ks * 8 + tm;
            uint32_t ah[2][4], al[2][4];
#pragma unroll
            for (int mb = 0; mb < 2; mb++) {
                int rr = 32 * mg + 16 * mb + tg;
                ah[mb][0] = As_h[rr * 20 + ci];
                ah[mb][1] = As_h[(rr + 8) * 20 + ci];
                ah[mb][2] = As_h[rr * 20 + ci + 4];
                ah[mb][3] = As_h[(rr + 8) * 20 + ci + 4];
                al[mb][0] = As_l[rr * 20 + ci];
                al[mb][1] = As_l[(rr + 8) * 20 + ci];
                al[mb][2] = As_l[rr * 20 + ci + 4];
                al[mb][3] = As_l[(rr + 8) * 20 + ci + 4];
            }
#pragma unroll
            for (int nb = 0; nb < 8; nb++) {
                int rn = 64 * ng + 8 * nb + tg;
                uint32_t bh[2] = { Bs_h[rn * 20 + ci], Bs_h[rn * 20 + ci + 4] };
                uint32_t bl[2] = { Bs_l[rn * 20 + ci], Bs_l[rn * 20 + ci + 4] };
#pragma unroll
                for (int mb = 0; mb < 2; mb++) {
                    mma_bf16(acc[mb][nb], ah[mb], bh);
                    mma_bf16(acc[mb][nb], ah[mb], bl);
                    mma_bf16(acc[mb][nb], al[mb], bh);
                }
            }
        }
        __syncthreads();
    }

    // epilogue: bias, split, scatter to [h][b][l][hd]
#pragma unroll
    for (int mb = 0; mb < 2; mb++) {
        int r0 = m0 + 32 * mg + 16 * mb + tg;
#pragma unroll
        for (int nb = 0; nb < 8; nb++) {
            float* a = acc[mb][nb];
            int gcol = n0 + 64 * ng + 8 * nb + 2 * tm;
            int isK = gcol >> 9;
            const float* bias = isK ? bk : bq;
            int bi = gcol & 511;
            float b0 = bias[bi], b1 = bias[bi + 1];
            __nv_bfloat16* dh = isK ? Kh_g : Qh_g;
            __nv_bfloat16* dl = isK ? Kl_g : Ql_g;
            int hh = bi >> 6;
#pragma unroll
            for (int half = 0; half < 2; half++) {
                int r = r0 + 8 * half;
                int bb = r >> 11, l = r & 2047;
                float v0 = a[half * 2 + 0] + b0;
                float v1 = a[half * 2 + 1] + b1;
                uint32_t hi, lo;
                split2(v0, v1, hi, lo);
                size_t e = ((size_t)((hh * 4 + bb) * 2048 + l)) * 64 + (gcol & 63);
                *(uint32_t*)(dh + e) = hi;
                *(uint32_t*)(dl + e) = lo;
            }
        }
    }
}

// ============================================================
// flash: q-tile 128 x k-tile 64. Q hi/lo fragments in REGISTERS;
// K hi/lo in FOUR rotating 18KB smem buffers; TWO k-tiles per barrier
// region (halves barrier/re-phase overhead vs R9). 2 CTAs/SM.
// smem words: buf j at j*4608 (Kh 2304 + Kl 2304), merge at 18432.
// ============================================================
#define FL_SMEM ((18432 + 256) * 4)

__global__ __launch_bounds__(256, 2) void flash_kernel(float* __restrict__ out) {
    extern __shared__ uint32_t sm[];
    float* merge = (float*)(sm + 18432);   // 256 floats

    const int tid = threadIdx.x;
    const int w = tid >> 5, lane = tid & 31, tg = lane >> 2, tm = lane & 3;
    const int mg = w & 3, ng = w >> 2;
    const int q0 = blockIdx.x * 128;
    const int hb = blockIdx.y;
    const int h = hb >> 2;
    const size_t hb_off = (size_t)hb * 2048;

    uint32_t smbase = (uint32_t)__cvta_generic_to_shared(sm);

    // K tile kt (64 seq rows, hi+lo) -> buffer bi (one cp.async group)
    auto load_k = [&](int kt, int bi) {
        const char* gh = (const char*)(Kh_g + (hb_off + (size_t)kt * 64) * 64);
        const char* gl = (const char*)(Kl_g + (hb_off + (size_t)kt * 64) * 64);
        uint32_t dh = smbase + (uint32_t)bi * 18432u;
        uint32_t dl = dh + 9216u;
#pragma unroll
        for (int i = 0; i < 2; i++) {
            int idx = i * 256 + tid;
            int row = idx >> 3, c4 = idx & 7;
            uint32_t so = (uint32_t)(row * 36 + c4 * 4) * 4;
            size_t go = (size_t)row * 128 + c4 * 16;
            cpa16(dh + so, gh + go);
            cpa16(dl + so, gl + go);
        }
        cpa_commit();
    };

    // prologue: stage Q (hi->buf2 region, lo->buf3 region) as one group,
    // then K0->buf0, K1->buf1 as two more groups.
    {
        const char* qh = (const char*)(Qh_g + (hb_off + q0) * 64);
        const char* ql = (const char*)(Ql_g + (hb_off + q0) * 64);
#pragma unroll
        for (int i = 0; i < 4; i++) {
            int idx = i * 256 + tid;
            int row = idx >> 3, c4 = idx & 7;
            uint32_t so = (uint32_t)(row * 36 + c4 * 4) * 4;
            size_t go = (size_t)row * 128 + c4 * 16;
            cpa16(smbase + 36864u + so,  qh + go);   // buf2 region
            cpa16(smbase + 55296u + so,  ql + go);   // buf3 region
        }
        cpa_commit();
    }
    load_k(0, 0);
    load_k(1, 1);

    cpa_wait2();           // Q group complete (K0,K1 may still fly)
    __syncthreads();

    // Q fragments -> registers (once)
    uint32_t aqh[2][4][4], aql[2][4][4];
    {
        const uint32_t* Qs_h = sm + 9216;
        const uint32_t* Qs_l = sm + 13824;
#pragma unroll
        for (int mb = 0; mb < 2; mb++) {
            int rr = 32 * mg + 16 * mb + tg;
#pragma unroll
            for (int ks = 0; ks < 4; ks++) {
                int ci = ks * 8 + tm;
                aqh[mb][ks][0] = Qs_h[rr * 36 + ci];
                aqh[mb][ks][1] = Qs_h[(rr + 8) * 36 + ci];
                aqh[mb][ks][2] = Qs_h[rr * 36 + ci + 4];
                aqh[mb][ks][3] = Qs_h[(rr + 8) * 36 + ci + 4];
                aql[mb][ks][0] = Qs_l[rr * 36 + ci];
                aql[mb][ks][1] = Qs_l[(rr + 8) * 36 + ci];
                aql[mb][ks][2] = Qs_l[rr * 36 + ci + 4];
                aql[mb][ks][3] = Qs_l[(rr + 8) * 36 + ci + 4];
            }
        }
    }
    __syncthreads();       // all warps done reading staged Q (buf2/3 now free)

    float suml[4] = {0.f, 0.f, 0.f, 0.f};
    float sumd[4] = {0.f, 0.f, 0.f, 0.f};
    const float* pt = ptab_g + h * 4095 + 2047;

    // one k-tile: MMA from buffer + epilogue
    auto process_tile = [&](int kt) {
        const uint32_t* Kh = sm + (kt & 3) * 4608;
        const uint32_t* Kl = Kh + 2304;

        float acc[2][4][4];
#pragma unroll
        for (int mb = 0; mb < 2; mb++)
#pragma unroll
            for (int nb = 0; nb < 4; nb++)
#pragma unroll
                for (int j = 0; j < 4; j++) acc[mb][nb][j] = 0.f;

#pragma unroll
        for (int ks = 0; ks < 4; ks++) {
            const int ci = ks * 8 + tm;
#pragma unroll
            for (int nb = 0; nb < 4; nb++) {
                int rn = 32 * ng + 8 * nb + tg;
                uint32_t bh[2] = { Kh[rn * 36 + ci], Kh[rn * 36 + ci + 4] };
                uint32_t bl[2] = { Kl[rn * 36 + ci], Kl[rn * 36 + ci + 4] };
#pragma unroll
                for (int mb = 0; mb < 2; mb++) {
                    mma_bf16(acc[mb][nb], aqh[mb][ks], bh);
                    mma_bf16(acc[mb][nb], aqh[mb][ks], bl);
                    mma_bf16(acc[mb][nb], aql[mb][ks], bh);
                }
            }
        }

        const int k0 = kt * 64;
#pragma unroll
        for (int mb = 0; mb < 2; mb++) {
            const int r0 = q0 + 32 * mg + 16 * mb + tg;
#pragma unroll
            for (int nb = 0; nb < 4; nb++) {
                const float* a = acc[mb][nb];
                int d0 = k0 + 32 * ng + 8 * nb + 2 * tm - r0;
                float fd = (float)d0;
                float p0 = __expf(a[0] * __ldg(pt + d0));
                float p1 = __expf(a[1] * __ldg(pt + d0 + 1));
                float p2 = __expf(a[2] * __ldg(pt + d0 - 8));
                float p3 = __expf(a[3] * __ldg(pt + d0 - 7));
                suml[2 * mb]     += p0 + p1;
                sumd[2 * mb]     += fmaf(p1, fd + 1.f, p0 * fd);
                suml[2 * mb + 1] += p2 + p3;
                sumd[2 * mb + 1] += fmaf(p3, fd - 7.f, p2 * (fd - 8.f));
            }
        }
    };

#pragma unroll 1
    for (int kt = 0; kt < 32; kt += 2) {
        cpa_wait0();        // K(kt), K(kt+1) complete
        __syncthreads();    // publish; buffers (kt+2)&3,(kt+3)&3 free
        if (kt + 2 < 32) {
            load_k(kt + 2, (kt + 2) & 3);
            load_k(kt + 3, (kt + 3) & 3);
        }
        process_tile(kt);
        process_tile(kt + 1);
    }

    // reduce across the 4 lanes of each group (width-4 shuffles)
#pragma unroll
    for (int s = 0; s < 4; s++) {
        suml[s] += __shfl_xor_sync(0xffffffffu, suml[s], 1, 4);
        suml[s] += __shfl_xor_sync(0xffffffffu, suml[s], 2, 4);
        sumd[s] += __shfl_xor_sync(0xffffffffu, sumd[s], 1, 4);
        sumd[s] += __shfl_xor_sync(0xffffffffu, sumd[s], 2, 4);
    }

    // merge the two n-groups via smem
    if (ng == 0 && tm == 0) {
#pragma unroll
        for (int s = 0; s < 4; s++) {
            int rl = 32 * mg + 16 * (s >> 1) + 8 * (s & 1) + tg;
            merge[rl] = suml[s];
            merge[128 + rl] = sumd[s];
        }
    }
    __syncthreads();
    if (ng == 1 && tm == 0) {
#pragma unroll
        for (int s = 0; s < 4; s++) {
            int rl = 32 * mg + 16 * (s >> 1) + 8 * (s & 1) + tg;
            float Lm = merge[rl] + suml[s];
            float Dm = merge[128 + rl] + sumd[s];
            out[((size_t)(hb & 3) * 2048 + q0 + rl) * 8 + h] = Dm * INV_ML / Lm;
        }
    }
}

// ============================================================
extern "C" void kernel_launch(void* const* d_in, const int* in_sizes, int n_in,
                              void* d_out, int out_size)
{
    const float* x  = (const float*)d_in[0];
    const float* Wq = (const float*)d_in[1];
    const float* bq = (const float*)d_in[2];
    const float* Wk = (const float*)d_in[3];
    const float* bk = (const float*)d_in[4];
    const float* pm = (const float*)d_in[5];
    const float* ls = (const float*)d_in[6];
    float* out = (float*)d_out;

    cudaFuncSetAttribute(proj_kernel,
                         cudaFuncAttributeMaxDynamicSharedMemorySize, PJ_SMEM);
    cudaFuncSetAttribute(flash_kernel,
                         cudaFuncAttributeMaxDynamicSharedMemorySize, FL_SMEM);

    ptab_kernel<<<8, 512>>>(pm, ls);
    conv_x_kernel<<<2048, 256>>>(x);
    conv_w_kernel<<<dim3(16, 8, 2), dim3(32, 8)>>>(Wq, Wk);
    proj_kernel<<<dim3(64, 8), 256, PJ_SMEM>>>(bq, bk);
    flash_kernel<<<dim3(16, 32), 256, FL_SMEM>>>(out);
}

// round 12
// speedup vs baseline: 2.3223x; 1.5133x over previous
#include <cuda_runtime.h>
#include <cuda_bf16.h>
#include <cuda_fp16.h>
#include <cstdint>

#define B_   4
#define L_   2048
#define H_   8
#define HD_  64
#define SCALE 0.125f
#define INV_ML (1.0f/2048.0f)

// ---------- device scratch ----------
__device__ __nv_bfloat16 xh_g[8192*256];
__device__ __nv_bfloat16 xl_g[8192*256];
__device__ __nv_bfloat16 Wth_g[1024*256];   // [Wq^T ; Wk^T], rows=n, cols=k
__device__ __nv_bfloat16 Wtl_g[1024*256];
__device__ __half Qg[32*2048*64];           // fp16 Q in [h*4+b][l][hd]
__device__ __half Kg[32*2048*64];           // fp16 K in [h*4+b][l][hd]
__device__ float ptab_g[H_*4095];           // per-head SCALE*prior LUT

// ---------- helpers ----------
__device__ __forceinline__ void split2(float a, float b, uint32_t& hi, uint32_t& lo) {
    __nv_bfloat16 ah = __float2bfloat16(a), bh = __float2bfloat16(b);
    float ar = a - __bfloat162float(ah), br = b - __bfloat162float(bh);
    __nv_bfloat162 h2; h2.x = ah; h2.y = bh;
    __nv_bfloat162 l2; l2.x = __float2bfloat16(ar); l2.y = __float2bfloat16(br);
    hi = *(uint32_t*)&h2; lo = *(uint32_t*)&l2;
}

// volatile is load-bearing: R10 showed removing it regresses 1.5x.
__device__ __forceinline__ void mma_bf16(float c[4], const uint32_t a[4],
                                         const uint32_t b[2]) {
    asm volatile(
        "mma.sync.aligned.m16n8k16.row.col.f32.bf16.bf16.f32 "
        "{%0,%1,%2,%3}, {%4,%5,%6,%7}, {%8,%9}, {%0,%1,%2,%3};"
        : "+f"(c[0]), "+f"(c[1]), "+f"(c[2]), "+f"(c[3])
        : "r"(a[0]), "r"(a[1]), "r"(a[2]), "r"(a[3]), "r"(b[0]), "r"(b[1]));
}

__device__ __forceinline__ void mma_fp16(float c[4], const uint32_t a[4],
                                         const uint32_t b[2]) {
    asm volatile(
        "mma.sync.aligned.m16n8k16.row.col.f32.f16.f16.f32 "
        "{%0,%1,%2,%3}, {%4,%5,%6,%7}, {%8,%9}, {%0,%1,%2,%3};"
        : "+f"(c[0]), "+f"(c[1]), "+f"(c[2]), "+f"(c[3])
        : "r"(a[0]), "r"(a[1]), "r"(a[2]), "r"(a[3]), "r"(b[0]), "r"(b[1]));
}

__device__ __forceinline__ void cpa16(uint32_t d, const void* s) {
    asm volatile("cp.async.cg.shared.global [%0], [%1], 16;" :: "r"(d), "l"(s));
}
__device__ __forceinline__ void cpa_commit() {
    asm volatile("cp.async.commit_group;" ::: "memory");
}
__device__ __forceinline__ void cpa_wait0() {
    asm volatile("cp.async.wait_group 0;" ::: "memory");
}
__device__ __forceinline__ void cpa_wait1() {
    asm volatile("cp.async.wait_group 1;" ::: "memory");
}
__device__ __forceinline__ void cpa_wait2() {
    asm volatile("cp.async.wait_group 2;" ::: "memory");
}

// ============================================================
// prep kernels
// ============================================================
__global__ __launch_bounds__(512) void ptab_kernel(const float* __restrict__ pm,
                                                   const float* __restrict__ ls) {
    int h = blockIdx.x;
    float mean = pm[h];
    float inv_std = __expf(-ls[h]);
    float cnorm = SCALE * inv_std * 0.39894228f;
    for (int t = threadIdx.x; t < 4095; t += 512) {
        float dd = (float)(t - 2047) * INV_ML;
        float z = (dd - mean) * inv_std;
        ptab_g[h * 4095 + t] = cnorm * __expf(-0.5f * z * z);
    }
}

__global__ __launch_bounds__(256) void conv_x_kernel(const float* __restrict__ x) {
    int i = blockIdx.x * 256 + threadIdx.x;   // float4 index, 524288 total
    float4 v = ((const float4*)x)[i];
    uint32_t h0, l0, h1, l1;
    split2(v.x, v.y, h0, l0);
    split2(v.z, v.w, h1, l1);
    ((uint2*)xh_g)[i] = make_uint2(h0, h1);
    ((uint2*)xl_g)[i] = make_uint2(l0, l1);
}

__global__ void conv_w_kernel(const float* __restrict__ Wq,
                              const float* __restrict__ Wk) {
    __shared__ float t[32][33];
    const float* W = blockIdx.z ? Wk : Wq;
    int n0 = blockIdx.x * 32, k0 = blockIdx.y * 32;
    int tx = threadIdx.x, ty = threadIdx.y;
#pragma unroll
    for (int i = 0; i < 32; i += 8)
        t[ty + i][tx] = W[(size_t)(k0 + ty + i) * 512 + n0 + tx];
    __syncthreads();
#pragma unroll
    for (int i = 0; i < 32; i += 8) {
        int n = n0 + ty + i, k = k0 + tx;
        float v = t[tx][ty + i];
        __nv_bfloat16 h = __float2bfloat16(v);
        float r = v - __bfloat162float(h);
        size_t o = (size_t)(blockIdx.z * 512 + n) * 256 + k;
        Wth_g[o] = h;
        Wtl_g[o] = __float2bfloat16(r);
    }
}

// ============================================================
// proj: [xh|xl][8192,256] @ Wt^T (bf16 3-split, exact to ~2^-18)
// -> Q/K stored as fp16 in [h][b][l][hd].  2 CTAs/SM.
// ============================================================
#define PJ_SMEM (10240*4*2)

__global__ __launch_bounds__(256, 2) void proj_kernel(const float* __restrict__ bq,
                                                      const float* __restrict__ bk) {
    extern __shared__ uint32_t sm[];
    const int tid = threadIdx.x;
    const int w = tid >> 5, lane = tid & 31, tg = lane >> 2, tm = lane & 3;
    const int mg = w & 3, ng = w >> 2;
    const int m0 = blockIdx.x * 128, n0 = blockIdx.y * 128;

    uint32_t smbase = (uint32_t)__cvta_generic_to_shared(sm);

    auto load_chunk = [&](int c, int buf) {
        uint32_t dst = smbase + (uint32_t)buf * 40960u;
#pragma unroll
        for (int i = 0; i < 2; i++) {
            int idx = i * 256 + tid;
            int row = idx >> 2, c4 = idx & 3;
            uint32_t so = (uint32_t)(row * 20 + c4 * 4) * 4;
            size_t goA = ((size_t)(m0 + row) * 256 + c * 32 + c4 * 8) * 2;  // bytes
            size_t goB = ((size_t)(n0 + row) * 256 + c * 32 + c4 * 8) * 2;
            cpa16(dst + so,          (const char*)xh_g  + goA);
            cpa16(dst + 10240 + so,  (const char*)xl_g  + goA);
            cpa16(dst + 20480 + so,  (const char*)Wth_g + goB);
            cpa16(dst + 30720 + so,  (const char*)Wtl_g + goB);
        }
        cpa_commit();
    };

    float acc[2][8][4];
#pragma unroll
    for (int mb = 0; mb < 2; mb++)
#pragma unroll
        for (int nb = 0; nb < 8; nb++)
#pragma unroll
            for (int j = 0; j < 4; j++) acc[mb][nb][j] = 0.f;

    load_chunk(0, 0);

#pragma unroll 1
    for (int c = 0; c < 8; c++) {
        const int buf = c & 1;
        if (c < 7) {
            load_chunk(c + 1, buf ^ 1);
            cpa_wait1();
        } else {
            cpa_wait0();
        }
        __syncthreads();

        const uint32_t* As_h = sm + buf * 10240;
        const uint32_t* As_l = As_h + 2560;
        const uint32_t* Bs_h = As_h + 5120;
        const uint32_t* Bs_l = As_h + 7680;

#pragma unroll
        for (int ks = 0; ks < 2; ks++) {
            const int ci = ks * 8 + tm;
            uint32_t ah[2][4], al[2][4];
#pragma unroll
            for (int mb = 0; mb < 2; mb++) {
                int rr = 32 * mg + 16 * mb + tg;
                ah[mb][0] = As_h[rr * 20 + ci];
                ah[mb][1] = As_h[(rr + 8) * 20 + ci];
                ah[mb][2] = As_h[rr * 20 + ci + 4];
                ah[mb][3] = As_h[(rr + 8) * 20 + ci + 4];
                al[mb][0] = As_l[rr * 20 + ci];
                al[mb][1] = As_l[(rr + 8) * 20 + ci];
                al[mb][2] = As_l[rr * 20 + ci + 4];
                al[mb][3] = As_l[(rr + 8) * 20 + ci + 4];
            }
#pragma unroll
            for (int nb = 0; nb < 8; nb++) {
                int rn = 64 * ng + 8 * nb + tg;
                uint32_t bh[2] = { Bs_h[rn * 20 + ci], Bs_h[rn * 20 + ci + 4] };
                uint32_t bl[2] = { Bs_l[rn * 20 + ci], Bs_l[rn * 20 + ci + 4] };
#pragma unroll
                for (int mb = 0; mb < 2; mb++) {
                    mma_bf16(acc[mb][nb], ah[mb], bh);
                    mma_bf16(acc[mb][nb], ah[mb], bl);
                    mma_bf16(acc[mb][nb], al[mb], bh);
                }
            }
        }
        __syncthreads();
    }

    // epilogue: bias, convert to fp16, scatter to [h][b][l][hd]
#pragma unroll
    for (int mb = 0; mb < 2; mb++) {
        int r0 = m0 + 32 * mg + 16 * mb + tg;
#pragma unroll
        for (int nb = 0; nb < 8; nb++) {
            float* a = acc[mb][nb];
            int gcol = n0 + 64 * ng + 8 * nb + 2 * tm;
            int isK = gcol >> 9;
            const float* bias = isK ? bk : bq;
            int bi = gcol & 511;
            float b0 = bias[bi], b1 = bias[bi + 1];
            __half* dst = isK ? Kg : Qg;
            int hh = bi >> 6;
#pragma unroll
            for (int half = 0; half < 2; half++) {
                int r = r0 + 8 * half;
                int bb = r >> 11, l = r & 2047;
                __half2 hv;
                hv.x = __float2half(a[half * 2 + 0] + b0);
                hv.y = __float2half(a[half * 2 + 1] + b1);
                size_t e = ((size_t)((hh * 4 + bb) * 2048 + l)) * 64 + (gcol & 63);
                *(uint32_t*)(dst + e) = *(uint32_t*)&hv;
            }
        }
    }
}

// ============================================================
// flash: q-tile 128 x k-tile 64, SINGLE fp16 MMA per fragment
// (precision budget: rel_err ~1e-4 << 1e-3 tolerance).
// Q fp16 fragments in registers; K fp16 in 4 rotating 9KB buffers.
// smem words: buf j at j*2304, merge at 9216.  2 CTAs/SM.
// ============================================================
#define FL_SMEM ((9216 + 256) * 4)

__global__ __launch_bounds__(256, 2) void flash_kernel(float* __restrict__ out) {
    extern __shared__ uint32_t sm[];
    float* merge = (float*)(sm + 9216);   // 256 floats

    const int tid = threadIdx.x;
    const int w = tid >> 5, lane = tid & 31, tg = lane >> 2, tm = lane & 3;
    const int mg = w & 3, ng = w >> 2;
    const int q0 = blockIdx.x * 128;
    const int hb = blockIdx.y;
    const int h = hb >> 2;
    const size_t hb_off = (size_t)hb * 2048;

    uint32_t smbase = (uint32_t)__cvta_generic_to_shared(sm);

    // K tile kt (64 seq rows fp16) -> buffer bi (one cp.async group)
    auto load_k = [&](int kt, int bi) {
        const char* gk = (const char*)(Kg + (hb_off + (size_t)kt * 64) * 64);
        uint32_t dk = smbase + (uint32_t)bi * 9216u;
#pragma unroll
        for (int i = 0; i < 2; i++) {
            int idx = i * 256 + tid;
            int row = idx >> 3, c4 = idx & 7;
            uint32_t so = (uint32_t)(row * 36 + c4 * 4) * 4;
            cpa16(dk + so, gk + (size_t)row * 128 + c4 * 16);
        }
        cpa_commit();
    };

    // prologue: stage Q (128 rows) into bufs 0-1 as one group; K0->buf2, K1->buf3
    {
        const char* gq = (const char*)(Qg + (hb_off + q0) * 64);
#pragma unroll
        for (int i = 0; i < 4; i++) {
            int idx = i * 256 + tid;
            int row = idx >> 3, c4 = idx & 7;
            uint32_t so = (uint32_t)(row * 36 + c4 * 4) * 4;
            cpa16(smbase + so, gq + (size_t)row * 128 + c4 * 16);
        }
        cpa_commit();
    }
    load_k(0, 2);
    load_k(1, 3);

    cpa_wait2();           // Q group complete (K0,K1 may still fly)
    __syncthreads();

    // Q fragments -> registers (once)
    uint32_t aq[2][4][4];
    {
        const uint32_t* Qs = sm;
#pragma unroll
        for (int mb = 0; mb < 2; mb++) {
            int rr = 32 * mg + 16 * mb + tg;
#pragma unroll
            for (int ks = 0; ks < 4; ks++) {
                int ci = ks * 8 + tm;
                aq[mb][ks][0] = Qs[rr * 36 + ci];
                aq[mb][ks][1] = Qs[(rr + 8) * 36 + ci];
                aq[mb][ks][2] = Qs[rr * 36 + ci + 4];
                aq[mb][ks][3] = Qs[(rr + 8) * 36 + ci + 4];
            }
        }
    }
    __syncthreads();       // all warps done reading staged Q (bufs 0-1 free)

    float suml[4] = {0.f, 0.f, 0.f, 0.f};
    float sumd[4] = {0.f, 0.f, 0.f, 0.f};
    const float* pt = ptab_g + h * 4095 + 2047;

    // one k-tile: single-MMA QK^T + epilogue.  buffer = (kt+2)&3
    auto process_tile = [&](int kt) {
        const uint32_t* Kh = sm + ((kt + 2) & 3) * 2304;

        float acc[2][4][4];
#pragma unroll
        for (int mb = 0; mb < 2; mb++)
#pragma unroll
            for (int nb = 0; nb < 4; nb++)
#pragma unroll
                for (int j = 0; j < 4; j++) acc[mb][nb][j] = 0.f;

#pragma unroll
        for (int ks = 0; ks < 4; ks++) {
            const int ci = ks * 8 + tm;
#pragma unroll
            for (int nb = 0; nb < 4; nb++) {
                int rn = 32 * ng + 8 * nb + tg;
                uint32_t bh[2] = { Kh[rn * 36 + ci], Kh[rn * 36 + ci + 4] };
#pragma unroll
                for (int mb = 0; mb < 2; mb++)
                    mma_fp16(acc[mb][nb], aq[mb][ks], bh);
            }
        }

        const int k0 = kt * 64;
#pragma unroll
        for (int mb = 0; mb < 2; mb++) {
            const int r0 = q0 + 32 * mg + 16 * mb + tg;
#pragma unroll
            for (int nb = 0; nb < 4; nb++) {
                const float* a = acc[mb][nb];
                int d0 = k0 + 32 * ng + 8 * nb + 2 * tm - r0;
                float fd = (float)d0;
                float p0 = __expf(a[0] * __ldg(pt + d0));
                float p1 = __expf(a[1] * __ldg(pt + d0 + 1));
                float p2 = __expf(a[2] * __ldg(pt + d0 - 8));
                float p3 = __expf(a[3] * __ldg(pt + d0 - 7));
                suml[2 * mb]     += p0 + p1;
                sumd[2 * mb]     += fmaf(p1, fd + 1.f, p0 * fd);
                suml[2 * mb + 1] += p2 + p3;
                sumd[2 * mb + 1] += fmaf(p3, fd - 7.f, p2 * (fd - 8.f));
            }
        }
    };

#pragma unroll 1
    for (int kt = 0; kt < 32; kt += 2) {
        cpa_wait0();        // K(kt), K(kt+1) complete
        __syncthreads();    // publish; buffers kt&3, (kt+1)&3 free
        if (kt + 2 < 32) {
            load_k(kt + 2, kt & 3);
            load_k(kt + 3, (kt + 1) & 3);
        }
        process_tile(kt);
        process_tile(kt + 1);
    }

    // reduce across the 4 lanes of each group (width-4 shuffles)
#pragma unroll
    for (int s = 0; s < 4; s++) {
        suml[s] += __shfl_xor_sync(0xffffffffu, suml[s], 1, 4);
        suml[s] += __shfl_xor_sync(0xffffffffu, suml[s], 2, 4);
        sumd[s] += __shfl_xor_sync(0xffffffffu, sumd[s], 1, 4);
        sumd[s] += __shfl_xor_sync(0xffffffffu, sumd[s], 2, 4);
    }

    // merge the two n-groups via smem
    if (ng == 0 && tm == 0) {
#pragma unroll
        for (int s = 0; s < 4; s++) {
            int rl = 32 * mg + 16 * (s >> 1) + 8 * (s & 1) + tg;
            merge[rl] = suml[s];
            merge[128 + rl] = sumd[s];
        }
    }
    __syncthreads();
    if (ng == 1 && tm == 0) {
#pragma unroll
        for (int s = 0; s < 4; s++) {
            int rl = 32 * mg + 16 * (s >> 1) + 8 * (s & 1) + tg;
            float Lm = merge[rl] + suml[s];
            float Dm = merge[128 + rl] + sumd[s];
            out[((size_t)(hb & 3) * 2048 + q0 + rl) * 8 + h] = Dm * INV_ML / Lm;
        }
    }
}

// ============================================================
extern "C" void kernel_launch(void* const* d_in, const int* in_sizes, int n_in,
                              void* d_out, int out_size)
{
    const float* x  = (const float*)d_in[0];
    const float* Wq = (const float*)d_in[1];
    const float* bq = (const float*)d_in[2];
    const float* Wk = (const float*)d_in[3];
    const float* bk = (const float*)d_in[4];
    const float* pm = (const float*)d_in[5];
    const float* ls = (const float*)d_in[6];
    float* out = (float*)d_out;

    cudaFuncSetAttribute(proj_kernel,
                         cudaFuncAttributeMaxDynamicSharedMemorySize, PJ_SMEM);
    cudaFuncSetAttribute(flash_kernel,
                         cudaFuncAttributeMaxDynamicSharedMemorySize, FL_SMEM);

    ptab_kernel<<<8, 512>>>(pm, ls);
    conv_x_kernel<<<2048, 256>>>(x);
    conv_w_kernel<<<dim3(16, 8, 2), dim3(32, 8)>>>(Wq, Wk);
    proj_kernel<<<dim3(64, 8), 256, PJ_SMEM>>>(bq, bk);
    flash_kernel<<<dim3(16, 32), 256, FL_SMEM>>>(out);
}

// round 13
// speedup vs baseline: 2.8475x; 1.2262x over previous
#include <cuda_runtime.h>
#include <cuda_bf16.h>
#include <cuda_fp16.h>
#include <cstdint>

#define B_   4
#define L_   2048
#define H_   8
#define HD_  64
#define SCALE 0.125f
#define INV_ML (1.0f/2048.0f)

// ---------- device scratch ----------
__device__ __half x16_g[8192*256];          // x as fp16
__device__ __half Wt16_g[1024*256];         // [Wq^T ; Wk^T] fp16, rows=n, cols=k
__device__ __half Qg[32*2048*64];           // fp16 Q in [h*4+b][l][hd]
__device__ __half Kg[32*2048*64];           // fp16 K in [h*4+b][l][hd]
__device__ float ptab_g[H_*4095];           // per-head SCALE*prior LUT

// ---------- helpers ----------
// volatile is load-bearing: R10 showed removing it regresses 1.5x.
__device__ __forceinline__ void mma_fp16(float c[4], const uint32_t a[4],
                                         const uint32_t b[2]) {
    asm volatile(
        "mma.sync.aligned.m16n8k16.row.col.f32.f16.f16.f32 "
        "{%0,%1,%2,%3}, {%4,%5,%6,%7}, {%8,%9}, {%0,%1,%2,%3};"
        : "+f"(c[0]), "+f"(c[1]), "+f"(c[2]), "+f"(c[3])
        : "r"(a[0]), "r"(a[1]), "r"(a[2]), "r"(a[3]), "r"(b[0]), "r"(b[1]));
}

__device__ __forceinline__ void cpa16(uint32_t d, const void* s) {
    asm volatile("cp.async.cg.shared.global [%0], [%1], 16;" :: "r"(d), "l"(s));
}
__device__ __forceinline__ void cpa_commit() {
    asm volatile("cp.async.commit_group;" ::: "memory");
}
__device__ __forceinline__ void cpa_wait0() {
    asm volatile("cp.async.wait_group 0;" ::: "memory");
}
__device__ __forceinline__ void cpa_wait1() {
    asm volatile("cp.async.wait_group 1;" ::: "memory");
}
__device__ __forceinline__ void cpa_wait2() {
    asm volatile("cp.async.wait_group 2;" ::: "memory");
}

// ============================================================
// prep kernels
// ============================================================
__global__ __launch_bounds__(512) void ptab_kernel(const float* __restrict__ pm,
                                                   const float* __restrict__ ls) {
    int h = blockIdx.x;
    float mean = pm[h];
    float inv_std = __expf(-ls[h]);
    float cnorm = SCALE * inv_std * 0.39894228f;
    for (int t = threadIdx.x; t < 4095; t += 512) {
        float dd = (float)(t - 2047) * INV_ML;
        float z = (dd - mean) * inv_std;
        ptab_g[h * 4095 + t] = cnorm * __expf(-0.5f * z * z);
    }
}

__global__ __launch_bounds__(256) void conv_x_kernel(const float* __restrict__ x) {
    int i = blockIdx.x * 256 + threadIdx.x;   // float4 index, 524288 total
    float4 v = ((const float4*)x)[i];
    __half2 a, b;
    a.x = __float2half(v.x); a.y = __float2half(v.y);
    b.x = __float2half(v.z); b.y = __float2half(v.w);
    ((uint2*)x16_g)[i] = make_uint2(*(uint32_t*)&a, *(uint32_t*)&b);
}

__global__ void conv_w_kernel(const float* __restrict__ Wq,
                              const float* __restrict__ Wk) {
    __shared__ float t[32][33];
    const float* W = blockIdx.z ? Wk : Wq;
    int n0 = blockIdx.x * 32, k0 = blockIdx.y * 32;
    int tx = threadIdx.x, ty = threadIdx.y;
#pragma unroll
    for (int i = 0; i < 32; i += 8)
        t[ty + i][tx] = W[(size_t)(k0 + ty + i) * 512 + n0 + tx];
    __syncthreads();
#pragma unroll
    for (int i = 0; i < 32; i += 8) {
        int n = n0 + ty + i, k = k0 + tx;
        size_t o = (size_t)(blockIdx.z * 512 + n) * 256 + k;
        Wt16_g[o] = __float2half(t[tx][ty + i]);
    }
}

// ============================================================
// proj: x16[8192,256] @ Wt16^T -> Q/K fp16 in [h][b][l][hd]
// CTA 128x128, k-chunk 64, double-buffered, single fp16 MMA, 2 CTAs/SM.
// Buffer (words): A [128][36]=4608, B same; buf stride 9216.
// ============================================================
#define PJ_SMEM (18432*4)

__global__ __launch_bounds__(256, 2) void proj_kernel(const float* __restrict__ bq,
                                                      const float* __restrict__ bk) {
    extern __shared__ uint32_t sm[];
    const int tid = threadIdx.x;
    const int w = tid >> 5, lane = tid & 31, tg = lane >> 2, tm = lane & 3;
    const int mg = w & 3, ng = w >> 2;
    const int m0 = blockIdx.x * 128, n0 = blockIdx.y * 128;

    uint32_t smbase = (uint32_t)__cvta_generic_to_shared(sm);

    auto load_chunk = [&](int c, int buf) {
        uint32_t dst = smbase + (uint32_t)buf * 36864u;
#pragma unroll
        for (int i = 0; i < 4; i++) {
            int idx = i * 256 + tid;
            int row = idx >> 3, c4 = idx & 7;
            uint32_t so = (uint32_t)(row * 36 + c4 * 4) * 4;
            size_t goA = ((size_t)(m0 + row) * 256 + c * 64) * 2 + c4 * 16;  // bytes
            size_t goB = ((size_t)(n0 + row) * 256 + c * 64) * 2 + c4 * 16;
            cpa16(dst + so,          (const char*)x16_g  + goA);
            cpa16(dst + 18432 + so,  (const char*)Wt16_g + goB);
        }
        cpa_commit();
    };

    float acc[2][8][4];
#pragma unroll
    for (int mb = 0; mb < 2; mb++)
#pragma unroll
        for (int nb = 0; nb < 8; nb++)
#pragma unroll
            for (int j = 0; j < 4; j++) acc[mb][nb][j] = 0.f;

    load_chunk(0, 0);

#pragma unroll 1
    for (int c = 0; c < 4; c++) {
        const int buf = c & 1;
        if (c < 3) {
            load_chunk(c + 1, buf ^ 1);
            cpa_wait1();
        } else {
            cpa_wait0();
        }
        __syncthreads();

        const uint32_t* As = sm + buf * 9216;
        const uint32_t* Bs = As + 4608;

#pragma unroll
        for (int ks = 0; ks < 4; ks++) {
            const int ci = ks * 8 + tm;
            uint32_t ah[2][4];
#pragma unroll
            for (int mb = 0; mb < 2; mb++) {
                int rr = 32 * mg + 16 * mb + tg;
                ah[mb][0] = As[rr * 36 + ci];
                ah[mb][1] = As[(rr + 8) * 36 + ci];
                ah[mb][2] = As[rr * 36 + ci + 4];
                ah[mb][3] = As[(rr + 8) * 36 + ci + 4];
            }
#pragma unroll
            for (int nb = 0; nb < 8; nb++) {
                int rn = 64 * ng + 8 * nb + tg;
                uint32_t bh[2] = { Bs[rn * 36 + ci], Bs[rn * 36 + ci + 4] };
#pragma unroll
                for (int mb = 0; mb < 2; mb++)
                    mma_fp16(acc[mb][nb], ah[mb], bh);
            }
        }
        __syncthreads();
    }

    // epilogue: bias, convert to fp16, scatter to [h][b][l][hd]
#pragma unroll
    for (int mb = 0; mb < 2; mb++) {
        int r0 = m0 + 32 * mg + 16 * mb + tg;
#pragma unroll
        for (int nb = 0; nb < 8; nb++) {
            float* a = acc[mb][nb];
            int gcol = n0 + 64 * ng + 8 * nb + 2 * tm;
            int isK = gcol >> 9;
            const float* bias = isK ? bk : bq;
            int bi = gcol & 511;
            float b0 = bias[bi], b1 = bias[bi + 1];
            __half* dst = isK ? Kg : Qg;
            int hh = bi >> 6;
#pragma unroll
            for (int half = 0; half < 2; half++) {
                int r = r0 + 8 * half;
                int bb = r >> 11, l = r & 2047;
                __half2 hv;
                hv.x = __float2half(a[half * 2 + 0] + b0);
                hv.y = __float2half(a[half * 2 + 1] + b1);
                size_t e = ((size_t)((hh * 4 + bb) * 2048 + l)) * 64 + (gcol & 63);
                *(uint32_t*)(dst + e) = *(uint32_t*)&hv;
            }
        }
    }
}

// ============================================================
// flash: q-tile 128 x k-tile 64, single fp16 MMA (R12 winner, unchanged).
// Q fp16 fragments in registers; K fp16 in 4 rotating 9KB buffers.
// smem words: buf j at j*2304, merge at 9216.  2 CTAs/SM.
// ============================================================
#define FL_SMEM ((9216 + 256) * 4)

__global__ __launch_bounds__(256, 2) void flash_kernel(float* __restrict__ out) {
    extern __shared__ uint32_t sm[];
    float* merge = (float*)(sm + 9216);   // 256 floats

    const int tid = threadIdx.x;
    const int w = tid >> 5, lane = tid & 31, tg = lane >> 2, tm = lane & 3;
    const int mg = w & 3, ng = w >> 2;
    const int q0 = blockIdx.x * 128;
    const int hb = blockIdx.y;
    const int h = hb >> 2;
    const size_t hb_off = (size_t)hb * 2048;

    uint32_t smbase = (uint32_t)__cvta_generic_to_shared(sm);

    // K tile kt (64 seq rows fp16) -> buffer bi (one cp.async group)
    auto load_k = [&](int kt, int bi) {
        const char* gk = (const char*)(Kg + (hb_off + (size_t)kt * 64) * 64);
        uint32_t dk = smbase + (uint32_t)bi * 9216u;
#pragma unroll
        for (int i = 0; i < 2; i++) {
            int idx = i * 256 + tid;
            int row = idx >> 3, c4 = idx & 7;
            uint32_t so = (uint32_t)(row * 36 + c4 * 4) * 4;
            cpa16(dk + so, gk + (size_t)row * 128 + c4 * 16);
        }
        cpa_commit();
    };

    // prologue: stage Q (128 rows) into bufs 0-1 as one group; K0->buf2, K1->buf3
    {
        const char* gq = (const char*)(Qg + (hb_off + q0) * 64);
#pragma unroll
        for (int i = 0; i < 4; i++) {
            int idx = i * 256 + tid;
            int row = idx >> 3, c4 = idx & 7;
            uint32_t so = (uint32_t)(row * 36 + c4 * 4) * 4;
            cpa16(smbase + so, gq + (size_t)row * 128 + c4 * 16);
        }
        cpa_commit();
    }
    load_k(0, 2);
    load_k(1, 3);

    cpa_wait2();           // Q group complete (K0,K1 may still fly)
    __syncthreads();

    // Q fragments -> registers (once)
    uint32_t aq[2][4][4];
    {
        const uint32_t* Qs = sm;
#pragma unroll
        for (int mb = 0; mb < 2; mb++) {
            int rr = 32 * mg + 16 * mb + tg;
#pragma unroll
            for (int ks = 0; ks < 4; ks++) {
                int ci = ks * 8 + tm;
                aq[mb][ks][0] = Qs[rr * 36 + ci];
                aq[mb][ks][1] = Qs[(rr + 8) * 36 + ci];
                aq[mb][ks][2] = Qs[rr * 36 + ci + 4];
                aq[mb][ks][3] = Qs[(rr + 8) * 36 + ci + 4];
            }
        }
    }
    __syncthreads();       // all warps done reading staged Q (bufs 0-1 free)

    float suml[4] = {0.f, 0.f, 0.f, 0.f};
    float sumd[4] = {0.f, 0.f, 0.f, 0.f};
    const float* pt = ptab_g + h * 4095 + 2047;

    // one k-tile: single-MMA QK^T + epilogue.  buffer = (kt+2)&3
    auto process_tile = [&](int kt) {
        const uint32_t* Kh = sm + ((kt + 2) & 3) * 2304;

        float acc[2][4][4];
#pragma unroll
        for (int mb = 0; mb < 2; mb++)
#pragma unroll
            for (int nb = 0; nb < 4; nb++)
#pragma unroll
                for (int j = 0; j < 4; j++) acc[mb][nb][j] = 0.f;

#pragma unroll
        for (int ks = 0; ks < 4; ks++) {
            const int ci = ks * 8 + tm;
#pragma unroll
            for (int nb = 0; nb < 4; nb++) {
                int rn = 32 * ng + 8 * nb + tg;
                uint32_t bh[2] = { Kh[rn * 36 + ci], Kh[rn * 36 + ci + 4] };
#pragma unroll
                for (int mb = 0; mb < 2; mb++)
                    mma_fp16(acc[mb][nb], aq[mb][ks], bh);
            }
        }

        const int k0 = kt * 64;
#pragma unroll
        for (int mb = 0; mb < 2; mb++) {
            const int r0 = q0 + 32 * mg + 16 * mb + tg;
#pragma unroll
            for (int nb = 0; nb < 4; nb++) {
                const float* a = acc[mb][nb];
                int d0 = k0 + 32 * ng + 8 * nb + 2 * tm - r0;
                float fd = (float)d0;
                float p0 = __expf(a[0] * __ldg(pt + d0));
                float p1 = __expf(a[1] * __ldg(pt + d0 + 1));
                float p2 = __expf(a[2] * __ldg(pt + d0 - 8));
                float p3 = __expf(a[3] * __ldg(pt + d0 - 7));
                suml[2 * mb]     += p0 + p1;
                sumd[2 * mb]     += fmaf(p1, fd + 1.f, p0 * fd);
                suml[2 * mb + 1] += p2 + p3;
                sumd[2 * mb + 1] += fmaf(p3, fd - 7.f, p2 * (fd - 8.f));
            }
        }
    };

#pragma unroll 1
    for (int kt = 0; kt < 32; kt += 2) {
        cpa_wait0();        // K(kt), K(kt+1) complete
        __syncthreads();    // publish; buffers kt&3, (kt+1)&3 free
        if (kt + 2 < 32) {
            load_k(kt + 2, kt & 3);
            load_k(kt + 3, (kt + 1) & 3);
        }
        process_tile(kt);
        process_tile(kt + 1);
    }

    // reduce across the 4 lanes of each group (width-4 shuffles)
#pragma unroll
    for (int s = 0; s < 4; s++) {
        suml[s] += __shfl_xor_sync(0xffffffffu, suml[s], 1, 4);
        suml[s] += __shfl_xor_sync(0xffffffffu, suml[s], 2, 4);
        sumd[s] += __shfl_xor_sync(0xffffffffu, sumd[s], 1, 4);
        sumd[s] += __shfl_xor_sync(0xffffffffu, sumd[s], 2, 4);
    }

    // merge the two n-groups via smem
    if (ng == 0 && tm == 0) {
#pragma unroll
        for (int s = 0; s < 4; s++) {
            int rl = 32 * mg + 16 * (s >> 1) + 8 * (s & 1) + tg;
            merge[rl] = suml[s];
            merge[128 + rl] = sumd[s];
        }
    }
    __syncthreads();
    if (ng == 1 && tm == 0) {
#pragma unroll
        for (int s = 0; s < 4; s++) {
            int rl = 32 * mg + 16 * (s >> 1) + 8 * (s & 1) + tg;
            float Lm = merge[rl] + suml[s];
            float Dm = merge[128 + rl] + sumd[s];
            out[((size_t)(hb & 3) * 2048 + q0 + rl) * 8 + h] = Dm * INV_ML / Lm;
        }
    }
}

// ============================================================
extern "C" void kernel_launch(void* const* d_in, const int* in_sizes, int n_in,
                              void* d_out, int out_size)
{
    const float* x  = (const float*)d_in[0];
    const float* Wq = (const float*)d_in[1];
    const float* bq = (const float*)d_in[2];
    const float* Wk = (const float*)d_in[3];
    const float* bk = (const float*)d_in[4];
    const float* pm = (const float*)d_in[5];
    const float* ls = (const float*)d_in[6];
    float* out = (float*)d_out;

    cudaFuncSetAttribute(proj_kernel,
                         cudaFuncAttributeMaxDynamicSharedMemorySize, PJ_SMEM);
    cudaFuncSetAttribute(flash_kernel,
                         cudaFuncAttributeMaxDynamicSharedMemorySize, FL_SMEM);

    ptab_kernel<<<8, 512>>>(pm, ls);
    conv_x_kernel<<<2048, 256>>>(x);
    conv_w_kernel<<<dim3(16, 8, 2), dim3(32, 8)>>>(Wq, Wk);
    proj_kernel<<<dim3(64, 8), 256, PJ_SMEM>>>(bq, bk);
    flash_kernel<<<dim3(16, 32), 256, FL_SMEM>>>(out);
}

// round 14
// speedup vs baseline: 3.2527x; 1.1423x over previous
#include <cuda_runtime.h>
#include <cuda_fp16.h>
#include <cstdint>

#define B_   4
#define L_   2048
#define H_   8
#define HD_  64
#define SCALE 0.125f
#define INV_ML (1.0f/2048.0f)

// ---------- device scratch ----------
__device__ __half x16_g[8192*256];          // x as fp16
__device__ __half Wt16_g[1024*256];         // [Wq^T ; Wk^T] fp16, rows=n, cols=k
__device__ __half Qg[32*2048*64];           // fp16 Q in [h*4+b][l][hd]
__device__ __half Kg[32*2048*64];           // fp16 K in [h*4+b][l][hd]
__device__ float ptab_g[H_*4095];           // per-head SCALE*prior LUT
__device__ float partL_g[2*32*2048];        // kv-split partial sum(p)
__device__ float partD_g[2*32*2048];        // kv-split partial sum(p*d)

// ---------- helpers ----------
// volatile is load-bearing: R10 showed removing it regresses 1.5x.
__device__ __forceinline__ void mma_fp16(float c[4], const uint32_t a[4],
                                         const uint32_t b[2]) {
    asm volatile(
        "mma.sync.aligned.m16n8k16.row.col.f32.f16.f16.f32 "
        "{%0,%1,%2,%3}, {%4,%5,%6,%7}, {%8,%9}, {%0,%1,%2,%3};"
        : "+f"(c[0]), "+f"(c[1]), "+f"(c[2]), "+f"(c[3])
        : "r"(a[0]), "r"(a[1]), "r"(a[2]), "r"(a[3]), "r"(b[0]), "r"(b[1]));
}

__device__ __forceinline__ void cpa16(uint32_t d, const void* s) {
    asm volatile("cp.async.cg.shared.global [%0], [%1], 16;" :: "r"(d), "l"(s));
}
__device__ __forceinline__ void cpa_commit() {
    asm volatile("cp.async.commit_group;" ::: "memory");
}
__device__ __forceinline__ void cpa_wait0() {
    asm volatile("cp.async.wait_group 0;" ::: "memory");
}
__device__ __forceinline__ void cpa_wait1() {
    asm volatile("cp.async.wait_group 1;" ::: "memory");
}
__device__ __forceinline__ void cpa_wait2() {
    asm volatile("cp.async.wait_group 2;" ::: "memory");
}

// ============================================================
// merged prep: blocks [0,2048) convert x, [2048,2304) transpose W,
// [2304,2312) build prior LUT.  One launch.
// ============================================================
__global__ __launch_bounds__(256) void prep_kernel(
    const float* __restrict__ x,
    const float* __restrict__ Wq, const float* __restrict__ Wk,
    const float* __restrict__ pm, const float* __restrict__ ls)
{
    const int bx = blockIdx.x;
    const int tid = threadIdx.x;

    if (bx < 2048) {                       // x -> fp16
        int i = bx * 256 + tid;            // float4 index, 524288 total
        float4 v = ((const float4*)x)[i];
        __half2 a, b;
        a.x = __float2half(v.x); a.y = __float2half(v.y);
        b.x = __float2half(v.z); b.y = __float2half(v.w);
        ((uint2*)x16_g)[i] = make_uint2(*(uint32_t*)&a, *(uint32_t*)&b);
    } else if (bx < 2304) {                // W transpose -> fp16
        __shared__ float t[32][33];
        int bidx = bx - 2048;
        int z = bidx >> 7, rest = bidx & 127;
        int n0 = (rest & 15) * 32, k0 = (rest >> 4) * 32;
        const float* W = z ? Wk : Wq;
        int tx = tid & 31, ty = tid >> 5;
#pragma unroll
        for (int i = 0; i < 32; i += 8)
            t[ty + i][tx] = W[(size_t)(k0 + ty + i) * 512 + n0 + tx];
        __syncthreads();
#pragma unroll
        for (int i = 0; i < 32; i += 8) {
            int n = n0 + ty + i, k = k0 + tx;
            size_t o = (size_t)(z * 512 + n) * 256 + k;
            Wt16_g[o] = __float2half(t[tx][ty + i]);
        }
    } else {                               // prior LUT
        int h = bx - 2304;
        float mean = pm[h];
        float inv_std = __expf(-ls[h]);
        float cnorm = SCALE * inv_std * 0.39894228f;
        for (int t2 = tid; t2 < 4095; t2 += 256) {
            float dd = (float)(t2 - 2047) * INV_ML;
            float z2 = (dd - mean) * inv_std;
            ptab_g[h * 4095 + t2] = cnorm * __expf(-0.5f * z2 * z2);
        }
    }
}

// ============================================================
// proj: x16[8192,256] @ Wt16^T -> Q/K fp16 in [h][b][l][hd]
// CTA 128x128, k-chunk 64, double-buffered, single fp16 MMA, 2 CTAs/SM.
// ============================================================
#define PJ_SMEM (18432*4)

__global__ __launch_bounds__(256, 2) void proj_kernel(const float* __restrict__ bq,
                                                      const float* __restrict__ bk) {
    extern __shared__ uint32_t sm[];
    const int tid = threadIdx.x;
    const int w = tid >> 5, lane = tid & 31, tg = lane >> 2, tm = lane & 3;
    const int mg = w & 3, ng = w >> 2;
    const int m0 = blockIdx.x * 128, n0 = blockIdx.y * 128;

    uint32_t smbase = (uint32_t)__cvta_generic_to_shared(sm);

    auto load_chunk = [&](int c, int buf) {
        uint32_t dst = smbase + (uint32_t)buf * 36864u;
#pragma unroll
        for (int i = 0; i < 4; i++) {
            int idx = i * 256 + tid;
            int row = idx >> 3, c4 = idx & 7;
            uint32_t so = (uint32_t)(row * 36 + c4 * 4) * 4;
            size_t goA = ((size_t)(m0 + row) * 256 + c * 64) * 2 + c4 * 16;  // bytes
            size_t goB = ((size_t)(n0 + row) * 256 + c * 64) * 2 + c4 * 16;
            cpa16(dst + so,          (const char*)x16_g  + goA);
            cpa16(dst + 18432 + so,  (const char*)Wt16_g + goB);
        }
        cpa_commit();
    };

    float acc[2][8][4];
#pragma unroll
    for (int mb = 0; mb < 2; mb++)
#pragma unroll
        for (int nb = 0; nb < 8; nb++)
#pragma unroll
            for (int j = 0; j < 4; j++) acc[mb][nb][j] = 0.f;

    load_chunk(0, 0);

#pragma unroll 1
    for (int c = 0; c < 4; c++) {
        const int buf = c & 1;
        if (c < 3) {
            load_chunk(c + 1, buf ^ 1);
            cpa_wait1();
        } else {
            cpa_wait0();
        }
        __syncthreads();

        const uint32_t* As = sm + buf * 9216;
        const uint32_t* Bs = As + 4608;

#pragma unroll
        for (int ks = 0; ks < 4; ks++) {
            const int ci = ks * 8 + tm;
            uint32_t ah[2][4];
#pragma unroll
            for (int mb = 0; mb < 2; mb++) {
                int rr = 32 * mg + 16 * mb + tg;
                ah[mb][0] = As[rr * 36 + ci];
                ah[mb][1] = As[(rr + 8) * 36 + ci];
                ah[mb][2] = As[rr * 36 + ci + 4];
                ah[mb][3] = As[(rr + 8) * 36 + ci + 4];
            }
#pragma unroll
            for (int nb = 0; nb < 8; nb++) {
                int rn = 64 * ng + 8 * nb + tg;
                uint32_t bh[2] = { Bs[rn * 36 + ci], Bs[rn * 36 + ci + 4] };
#pragma unroll
                for (int mb = 0; mb < 2; mb++)
                    mma_fp16(acc[mb][nb], ah[mb], bh);
            }
        }
        __syncthreads();
    }

    // epilogue: bias, convert to fp16, scatter to [h][b][l][hd]
#pragma unroll
    for (int mb = 0; mb < 2; mb++) {
        int r0 = m0 + 32 * mg + 16 * mb + tg;
#pragma unroll
        for (int nb = 0; nb < 8; nb++) {
            float* a = acc[mb][nb];
            int gcol = n0 + 64 * ng + 8 * nb + 2 * tm;
            int isK = gcol >> 9;
            const float* bias = isK ? bk : bq;
            int bi = gcol & 511;
            float b0 = bias[bi], b1 = bias[bi + 1];
            __half* dst = isK ? Kg : Qg;
            int hh = bi >> 6;
#pragma unroll
            for (int half = 0; half < 2; half++) {
                int r = r0 + 8 * half;
                int bb = r >> 11, l = r & 2047;
                __half2 hv;
                hv.x = __float2half(a[half * 2 + 0] + b0);
                hv.y = __float2half(a[half * 2 + 1] + b1);
                size_t e = ((size_t)((hh * 4 + bb) * 2048 + l)) * 64 + (gcol & 63);
                *(uint32_t*)(dst + e) = *(uint32_t*)&hv;
            }
        }
    }
}

// ============================================================
// flash: q-tile 128 x k-tile 64, single fp16 MMA, kv-split 2
// (blockIdx.z = split of 16 k-tiles). Partial (sumL, sumD) written to
// partL_g/partD_g per split; final_kernel combines (deterministic).
// Q fp16 fragments in registers; K fp16 in 4 rotating 9KB buffers.
// smem words: buf j at j*2304, merge at 9216.  2 CTAs/SM.
// ============================================================
#define FL_SMEM ((9216 + 256) * 4)

__global__ __launch_bounds__(256, 2) void flash_kernel() {
    extern __shared__ uint32_t sm[];
    float* merge = (float*)(sm + 9216);   // 256 floats

    const int tid = threadIdx.x;
    const int w = tid >> 5, lane = tid & 31, tg = lane >> 2, tm = lane & 3;
    const int mg = w & 3, ng = w >> 2;
    const int q0 = blockIdx.x * 128;
    const int hb = blockIdx.y;
    const int split = blockIdx.z;
    const int ktbase = split * 16;         // 16 k-tiles per split, base mod 4 == 0
    const int h = hb >> 2;
    const size_t hb_off = (size_t)hb * 2048;

    uint32_t smbase = (uint32_t)__cvta_generic_to_shared(sm);

    // K tile kt (64 seq rows fp16) -> buffer bi (one cp.async group)
    auto load_k = [&](int kt, int bi) {
        const char* gk = (const char*)(Kg + (hb_off + (size_t)kt * 64) * 64);
        uint32_t dk = smbase + (uint32_t)bi * 9216u;
#pragma unroll
        for (int i = 0; i < 2; i++) {
            int idx = i * 256 + tid;
            int row = idx >> 3, c4 = idx & 7;
            uint32_t so = (uint32_t)(row * 36 + c4 * 4) * 4;
            cpa16(dk + so, gk + (size_t)row * 128 + c4 * 16);
        }
        cpa_commit();
    };

    // prologue: stage Q (128 rows) into bufs 0-1; K(ktbase)->buf2, K(+1)->buf3
    {
        const char* gq = (const char*)(Qg + (hb_off + q0) * 64);
#pragma unroll
        for (int i = 0; i < 4; i++) {
            int idx = i * 256 + tid;
            int row = idx >> 3, c4 = idx & 7;
            uint32_t so = (uint32_t)(row * 36 + c4 * 4) * 4;
            cpa16(smbase + so, gq + (size_t)row * 128 + c4 * 16);
        }
        cpa_commit();
    }
    load_k(ktbase, 2);
    load_k(ktbase + 1, 3);

    cpa_wait2();           // Q group complete (K tiles may still fly)
    __syncthreads();

    // Q fragments -> registers (once)
    uint32_t aq[2][4][4];
    {
        const uint32_t* Qs = sm;
#pragma unroll
        for (int mb = 0; mb < 2; mb++) {
            int rr = 32 * mg + 16 * mb + tg;
#pragma unroll
            for (int ks = 0; ks < 4; ks++) {
                int ci = ks * 8 + tm;
                aq[mb][ks][0] = Qs[rr * 36 + ci];
                aq[mb][ks][1] = Qs[(rr + 8) * 36 + ci];
                aq[mb][ks][2] = Qs[rr * 36 + ci + 4];
                aq[mb][ks][3] = Qs[(rr + 8) * 36 + ci + 4];
            }
        }
    }
    __syncthreads();       // all warps done reading staged Q (bufs 0-1 free)

    float suml[4] = {0.f, 0.f, 0.f, 0.f};
    float sumd[4] = {0.f, 0.f, 0.f, 0.f};
    const float* pt = ptab_g + h * 4095 + 2047;

    // one k-tile: single-MMA QK^T + epilogue.  buffer = (kt+2)&3
    auto process_tile = [&](int kt) {
        const uint32_t* Kh = sm + ((kt + 2) & 3) * 2304;

        float acc[2][4][4];
#pragma unroll
        for (int mb = 0; mb < 2; mb++)
#pragma unroll
            for (int nb = 0; nb < 4; nb++)
#pragma unroll
                for (int j = 0; j < 4; j++) acc[mb][nb][j] = 0.f;

#pragma unroll
        for (int ks = 0; ks < 4; ks++) {
            const int ci = ks * 8 + tm;
#pragma unroll
            for (int nb = 0; nb < 4; nb++) {
                int rn = 32 * ng + 8 * nb + tg;
                uint32_t bh[2] = { Kh[rn * 36 + ci], Kh[rn * 36 + ci + 4] };
#pragma unroll
                for (int mb = 0; mb < 2; mb++)
                    mma_fp16(acc[mb][nb], aq[mb][ks], bh);
            }
        }

        const int k0 = kt * 64;
#pragma unroll
        for (int mb = 0; mb < 2; mb++) {
            const int r0 = q0 + 32 * mg + 16 * mb + tg;
#pragma unroll
            for (int nb = 0; nb < 4; nb++) {
                const float* a = acc[mb][nb];
                int d0 = k0 + 32 * ng + 8 * nb + 2 * tm - r0;
                float fd = (float)d0;
                float p0 = __expf(a[0] * __ldg(pt + d0));
                float p1 = __expf(a[1] * __ldg(pt + d0 + 1));
                float p2 = __expf(a[2] * __ldg(pt + d0 - 8));
                float p3 = __expf(a[3] * __ldg(pt + d0 - 7));
                suml[2 * mb]     += p0 + p1;
                sumd[2 * mb]     += fmaf(p1, fd + 1.f, p0 * fd);
                suml[2 * mb + 1] += p2 + p3;
                sumd[2 * mb + 1] += fmaf(p3, fd - 7.f, p2 * (fd - 8.f));
            }
        }
    };

#pragma unroll 1
    for (int kt = ktbase; kt < ktbase + 16; kt += 2) {
        cpa_wait0();        // K(kt), K(kt+1) complete
        __syncthreads();    // publish; buffers kt&3, (kt+1)&3 free
        if (kt + 2 < ktbase + 16) {
            load_k(kt + 2, kt & 3);
            load_k(kt + 3, (kt + 1) & 3);
        }
        process_tile(kt);
        process_tile(kt + 1);
    }

    // reduce across the 4 lanes of each group (width-4 shuffles)
#pragma unroll
    for (int s = 0; s < 4; s++) {
        suml[s] += __shfl_xor_sync(0xffffffffu, suml[s], 1, 4);
        suml[s] += __shfl_xor_sync(0xffffffffu, suml[s], 2, 4);
        sumd[s] += __shfl_xor_sync(0xffffffffu, sumd[s], 1, 4);
        sumd[s] += __shfl_xor_sync(0xffffffffu, sumd[s], 2, 4);
    }

    // merge the two n-groups via smem, then write split partials
    if (ng == 0 && tm == 0) {
#pragma unroll
        for (int s = 0; s < 4; s++) {
            int rl = 32 * mg + 16 * (s >> 1) + 8 * (s & 1) + tg;
            merge[rl] = suml[s];
            merge[128 + rl] = sumd[s];
        }
    }
    __syncthreads();
    if (ng == 1 && tm == 0) {
        const size_t pbase = ((size_t)split * 32 + hb) * 2048 + q0;
#pragma unroll
        for (int s = 0; s < 4; s++) {
            int rl = 32 * mg + 16 * (s >> 1) + 8 * (s & 1) + tg;
            partL_g[pbase + rl] = merge[rl] + suml[s];
            partD_g[pbase + rl] = merge[128 + rl] + sumd[s];
        }
    }
}

// ============================================================
// final: combine the two kv-splits and write output [b][l][h]
// ============================================================
__global__ __launch_bounds__(256) void final_kernel(float* __restrict__ out) {
    int idx = blockIdx.x * 256 + threadIdx.x;    // (hb*2048 + q), 65536 total
    int hb = idx >> 11, q = idx & 2047;
    int h = hb >> 2, b = hb & 3;
    float L = partL_g[idx] + partL_g[65536 + idx];
    float D = partD_g[idx] + partD_g[65536 + idx];
    out[((size_t)b * 2048 + q) * 8 + h] = D * INV_ML / L;
}

// ============================================================
extern "C" void kernel_launch(void* const* d_in, const int* in_sizes, int n_in,
                              void* d_out, int out_size)
{
    const float* x  = (const float*)d_in[0];
    const float* Wq = (const float*)d_in[1];
    const float* bq = (const float*)d_in[2];
    const float* Wk = (const float*)d_in[3];
    const float* bk = (const float*)d_in[4];
    const float* pm = (const float*)d_in[5];
    const float* ls = (const float*)d_in[6];
    float* out = (float*)d_out;

    cudaFuncSetAttribute(proj_kernel,
                         cudaFuncAttributeMaxDynamicSharedMemorySize, PJ_SMEM);
    cudaFuncSetAttribute(flash_kernel,
                         cudaFuncAttributeMaxDynamicSharedMemorySize, FL_SMEM);

    prep_kernel<<<2312, 256>>>(x, Wq, Wk, pm, ls);
    proj_kernel<<<dim3(64, 8), 256, PJ_SMEM>>>(bq, bk);
    flash_kernel<<<dim3(16, 32, 2), 256, FL_SMEM>>>();
    final_kernel<<<256, 256>>>(out);
}